// round 2
// baseline (speedup 1.0000x reference)
#include <cuda_runtime.h>
#include <cstdint>

#define D_MODEL 256
#define MAXE 160000
#define MAXN 10240

// ---------------- scratch (static device globals; no allocs allowed) ----------
__device__ float g_nQ1[MAXN * D_MODEL];
__device__ float g_nK1[MAXN * D_MODEL];
__device__ float g_nV1[MAXN * D_MODEL];
__device__ float g_nK2[MAXN * D_MODEL];
__device__ float g_nV2[MAXN * D_MODEL];
__device__ float g_e0[(size_t)MAXE * D_MODEL];
__device__ float g_e1[(size_t)MAXE * D_MODEL];
__device__ float g_big0[(size_t)MAXE * 3 * D_MODEL];
__device__ float g_big1[(size_t)MAXE * 3 * D_MODEL];
__device__ float g_alpha[MAXE];
__device__ float g_eexp[MAXE];
__device__ unsigned g_amax[MAXN];
__device__ float g_denom[MAXN];

// ---------------- helpers ----------------------------------------------------
__device__ __forceinline__ float warp_sum(float v) {
    #pragma unroll
    for (int o = 16; o > 0; o >>= 1) v += __shfl_xor_sync(0xFFFFFFFFu, v, o);
    return v;
}

// order-preserving float<->uint key for atomicMax on floats
__device__ __forceinline__ unsigned fkey(float f) {
    unsigned u = __float_as_uint(f);
    return (u & 0x80000000u) ? ~u : (u | 0x80000000u);
}
__device__ __forceinline__ float funkey(unsigned k) {
    unsigned u = (k & 0x80000000u) ? (k & 0x7FFFFFFFu) : ~k;
    return __uint_as_float(u);
}

// ---------------- GEMM: C[M,N] = act(A[M,K] @ W[N,K]^T + bias[N]) -------------
// 64x64 block tile, BK=16, 256 threads, 4x4 microtile.
template <int ACT>  // 0 = none, 1 = leaky relu (0.2)
__global__ __launch_bounds__(256)
void gemm_kernel(const float* __restrict__ A, const float* __restrict__ W,
                 const float* __restrict__ bias, float* __restrict__ C,
                 int M, int N, int K) {
    __shared__ float As[16][68];
    __shared__ float Bs[16][68];

    const int tid = threadIdx.x;
    const int tx = tid & 15;        // 0..15  -> 4 cols each
    const int ty = tid >> 4;        // 0..15  -> 4 rows each
    const int bx = blockIdx.x, by = blockIdx.y;

    const int lrow = tid >> 2;          // 0..63
    const int lk0  = (tid & 3) << 2;    // 0,4,8,12

    const int arow = by * 64 + lrow;
    const int wrow = bx * 64 + lrow;
    const bool aok = arow < M;
    const bool wok = wrow < N;
    const float* Ap = A + (size_t)arow * K;
    const float* Wp = W + (size_t)wrow * K;

    float acc[4][4];
    #pragma unroll
    for (int i = 0; i < 4; i++)
        #pragma unroll
        for (int j = 0; j < 4; j++) acc[i][j] = 0.f;

    for (int k0 = 0; k0 < K; k0 += 16) {
        float4 av = aok ? *(const float4*)(Ap + k0 + lk0) : make_float4(0.f, 0.f, 0.f, 0.f);
        float4 wv = wok ? *(const float4*)(Wp + k0 + lk0) : make_float4(0.f, 0.f, 0.f, 0.f);
        __syncthreads();
        As[lk0 + 0][lrow] = av.x; As[lk0 + 1][lrow] = av.y;
        As[lk0 + 2][lrow] = av.z; As[lk0 + 3][lrow] = av.w;
        Bs[lk0 + 0][lrow] = wv.x; Bs[lk0 + 1][lrow] = wv.y;
        Bs[lk0 + 2][lrow] = wv.z; Bs[lk0 + 3][lrow] = wv.w;
        __syncthreads();
        #pragma unroll
        for (int kk = 0; kk < 16; kk++) {
            float4 a = *(const float4*)&As[kk][ty * 4];
            float4 b = *(const float4*)&Bs[kk][tx * 4];
            acc[0][0] += a.x * b.x; acc[0][1] += a.x * b.y; acc[0][2] += a.x * b.z; acc[0][3] += a.x * b.w;
            acc[1][0] += a.y * b.x; acc[1][1] += a.y * b.y; acc[1][2] += a.y * b.z; acc[1][3] += a.y * b.w;
            acc[2][0] += a.z * b.x; acc[2][1] += a.z * b.y; acc[2][2] += a.z * b.z; acc[2][3] += a.z * b.w;
            acc[3][0] += a.w * b.x; acc[3][1] += a.w * b.y; acc[3][2] += a.w * b.z; acc[3][3] += a.w * b.w;
        }
    }

    const int row0 = by * 64 + ty * 4;
    const int col0 = bx * 64 + tx * 4;
    #pragma unroll
    for (int i = 0; i < 4; i++) {
        int r = row0 + i;
        if (r >= M) continue;
        #pragma unroll
        for (int j = 0; j < 4; j++) {
            int c = col0 + j;
            if (c >= N) continue;
            float v = acc[i][j] + bias[c];
            if (ACT == 1) v = v > 0.f ? v : 0.2f * v;
            C[(size_t)r * N + c] = v;
        }
    }
}

// ---------------- segment-softmax pieces --------------------------------------
__global__ void init_seg_kernel(unsigned* amax, float* denom, int n) {
    int i = blockIdx.x * blockDim.x + threadIdx.x;
    if (i < n) { amax[i] = 0u; denom[i] = 0.f; }
}

// alpha[e] = dot(Qrow, Krow); Qrow = Q[qidx[e]] (node-gather) or Q[e] (edge)
__global__ void alpha_kernel(const float* __restrict__ Q, const int* __restrict__ qidx,
                             const float* __restrict__ Kn,
                             const int* __restrict__ src, const int* __restrict__ dst,
                             float* __restrict__ alpha, unsigned* __restrict__ amax, int E) {
    int e = (blockIdx.x * blockDim.x + threadIdx.x) >> 5;
    int lane = threadIdx.x & 31;
    if (e >= E) return;
    const float* qr = Q + (size_t)(qidx ? qidx[e] : e) * D_MODEL;
    const float* kr = Kn + (size_t)src[e] * D_MODEL;
    float s = 0.f;
    #pragma unroll
    for (int i = 0; i < 8; i++) {
        int d = lane + 32 * i;
        s += qr[d] * kr[d];
    }
    s = warp_sum(s);
    if (lane == 0) {
        alpha[e] = s;
        atomicMax(&amax[dst[e]], fkey(s));
    }
}

__global__ void exp_denom_kernel(const float* __restrict__ alpha, const unsigned* __restrict__ amax,
                                 const int* __restrict__ dst,
                                 float* __restrict__ eexp, float* __restrict__ denom, int E) {
    int e = blockIdx.x * blockDim.x + threadIdx.x;
    if (e >= E) return;
    float m = funkey(amax[dst[e]]);
    float v = expf(alpha[e] - m);
    eexp[e] = v;
    atomicAdd(&denom[dst[e]], v);
}

// out[e,:] = LN(Qrow + attn*Vrow) ; warp per row
__global__ void attn_ln_kernel(const float* __restrict__ Q, const int* __restrict__ qidx,
                               const float* __restrict__ Vn,
                               const int* __restrict__ src, const int* __restrict__ dst,
                               const float* __restrict__ eexp, const float* __restrict__ denom,
                               const float* __restrict__ g, const float* __restrict__ b,
                               float* __restrict__ out, int E) {
    int e = (blockIdx.x * blockDim.x + threadIdx.x) >> 5;
    int lane = threadIdx.x & 31;
    if (e >= E) return;
    const float* qr = Q + (size_t)(qidx ? qidx[e] : e) * D_MODEL;
    const float* vr = Vn + (size_t)src[e] * D_MODEL;
    float attn = eexp[e] / denom[dst[e]];
    float vals[8];
    #pragma unroll
    for (int i = 0; i < 8; i++) {
        int d = lane + 32 * i;
        vals[i] = qr[d] + attn * vr[d];
    }
    float s = 0.f;
    #pragma unroll
    for (int i = 0; i < 8; i++) s += vals[i];
    float mean = warp_sum(s) * (1.f / 256.f);
    float q2 = 0.f;
    #pragma unroll
    for (int i = 0; i < 8; i++) { float t = vals[i] - mean; q2 += t * t; }
    float rstd = rsqrtf(warp_sum(q2) * (1.f / 256.f) + 1e-5f);
    float* orow = out + (size_t)e * D_MODEL;
    #pragma unroll
    for (int i = 0; i < 8; i++) {
        int d = lane + 32 * i;
        orow[d] = (vals[i] - mean) * rstd * g[d] + b[d];
    }
}

// out[e,:] = LN(lrelu(in[e,:])) ; warp per row
__global__ void lrelu_ln_kernel(const float* __restrict__ in,
                                const float* __restrict__ g, const float* __restrict__ b,
                                float* __restrict__ out, int E) {
    int e = (blockIdx.x * blockDim.x + threadIdx.x) >> 5;
    int lane = threadIdx.x & 31;
    if (e >= E) return;
    const float* ir = in + (size_t)e * D_MODEL;
    float vals[8];
    #pragma unroll
    for (int i = 0; i < 8; i++) {
        float v = ir[lane + 32 * i];
        vals[i] = v > 0.f ? v : 0.2f * v;
    }
    float s = 0.f;
    #pragma unroll
    for (int i = 0; i < 8; i++) s += vals[i];
    float mean = warp_sum(s) * (1.f / 256.f);
    float q2 = 0.f;
    #pragma unroll
    for (int i = 0; i < 8; i++) { float t = vals[i] - mean; q2 += t * t; }
    float rstd = rsqrtf(warp_sum(q2) * (1.f / 256.f) + 1e-5f);
    float* orow = out + (size_t)e * D_MODEL;
    #pragma unroll
    for (int i = 0; i < 8; i++) {
        int d = lane + 32 * i;
        orow[d] = (vals[i] - mean) * rstd * g[d] + b[d];
    }
}

// out[e] = dot(LN(h3[e,:]+qf[e,:], gfin, bfin), Wvec) + bvec ; warp per row
__global__ void final_kernel(const float* __restrict__ h3, const float* __restrict__ qf,
                             const float* __restrict__ g, const float* __restrict__ b,
                             const float* __restrict__ Wvec, const float* __restrict__ bvec,
                             float* __restrict__ out, int E) {
    int e = (blockIdx.x * blockDim.x + threadIdx.x) >> 5;
    int lane = threadIdx.x & 31;
    if (e >= E) return;
    const float* hr = h3 + (size_t)e * D_MODEL;
    const float* qr = qf + (size_t)e * D_MODEL;
    float vals[8];
    #pragma unroll
    for (int i = 0; i < 8; i++) {
        int d = lane + 32 * i;
        vals[i] = hr[d] + qr[d];
    }
    float s = 0.f;
    #pragma unroll
    for (int i = 0; i < 8; i++) s += vals[i];
    float mean = warp_sum(s) * (1.f / 256.f);
    float q2 = 0.f;
    #pragma unroll
    for (int i = 0; i < 8; i++) { float t = vals[i] - mean; q2 += t * t; }
    float rstd = rsqrtf(warp_sum(q2) * (1.f / 256.f) + 1e-5f);
    float dotv = 0.f;
    #pragma unroll
    for (int i = 0; i < 8; i++) {
        int d = lane + 32 * i;
        float hn = (vals[i] - mean) * rstd * g[d] + b[d];
        dotv += hn * Wvec[d];
    }
    dotv = warp_sum(dotv);
    if (lane == 0) out[e] = dotv + bvec[0];
}

// ---------------- launch ------------------------------------------------------
extern "C" void kernel_launch(void* const* d_in, const int* in_sizes, int n_in,
                              void* d_out, int out_size) {
    const int*   ei   = (const int*)d_in[0];
    const float* x    = (const float*)d_in[1];
    const float* Wq   = (const float*)d_in[2];
    const float* bq   = (const float*)d_in[3];
    const float* Wk   = (const float*)d_in[4];
    const float* bk   = (const float*)d_in[5];
    const float* Wv   = (const float*)d_in[6];
    const float* bv   = (const float*)d_in[7];
    const float* Wff  = (const float*)d_in[8];
    const float* bff  = (const float*)d_in[9];
    const float* ga   = (const float*)d_in[10];
    const float* ba   = (const float*)d_in[11];
    const float* gf   = (const float*)d_in[12];
    const float* bf   = (const float*)d_in[13];
    const float* gfin = (const float*)d_in[14];
    const float* bfin = (const float*)d_in[15];
    const float* W3   = (const float*)d_in[16];
    const float* b3   = (const float*)d_in[17];
    const float* W4   = (const float*)d_in[18];
    const float* b4   = (const float*)d_in[19];
    const float* W5   = (const float*)d_in[20];
    const float* b5   = (const float*)d_in[21];
    const float* Wvec = (const float*)d_in[22];
    const float* bvec = (const float*)d_in[23];
    float* out = (float*)d_out;

    const int E  = in_sizes[0] / 2;
    const int Nn = in_sizes[1] / D_MODEL;
    const int D  = D_MODEL;
    const int DD = D * D;
    const int* src = ei;
    const int* dst = ei + E;

    float *nQ1, *nK1, *nV1, *nK2, *nV2, *e0, *e1, *big0, *big1, *alpha, *eexp, *denom;
    unsigned* amax;
    cudaGetSymbolAddress((void**)&nQ1, g_nQ1);
    cudaGetSymbolAddress((void**)&nK1, g_nK1);
    cudaGetSymbolAddress((void**)&nV1, g_nV1);
    cudaGetSymbolAddress((void**)&nK2, g_nK2);
    cudaGetSymbolAddress((void**)&nV2, g_nV2);
    cudaGetSymbolAddress((void**)&e0, g_e0);
    cudaGetSymbolAddress((void**)&e1, g_e1);
    cudaGetSymbolAddress((void**)&big0, g_big0);
    cudaGetSymbolAddress((void**)&big1, g_big1);
    cudaGetSymbolAddress((void**)&alpha, g_alpha);
    cudaGetSymbolAddress((void**)&eexp, g_eexp);
    cudaGetSymbolAddress((void**)&amax, g_amax);
    cudaGetSymbolAddress((void**)&denom, g_denom);

    dim3 gNode(D / 64, (Nn + 63) / 64);
    dim3 gEdgeD(D / 64, (E + 63) / 64);
    dim3 gEdge3D(3 * D / 64, (E + 63) / 64);
    const int warpBlocks = (E * 32 + 255) / 256;
    const int thrBlocks = (E + 255) / 256;
    const int segBlocks = (Nn + 255) / 256;

    // node-level projections (16x FLOP saving vs edge-level)
    gemm_kernel<0><<<gNode, 256>>>(x, Wq,      bq,     nQ1, Nn, D, D);
    gemm_kernel<0><<<gNode, 256>>>(x, Wk,      bk,     nK1, Nn, D, D);
    gemm_kernel<0><<<gNode, 256>>>(x, Wv,      bv,     nV1, Nn, D, D);
    gemm_kernel<0><<<gNode, 256>>>(x, Wk + DD, bk + D, nK2, Nn, D, D);
    gemm_kernel<0><<<gNode, 256>>>(x, Wv + DD, bv + D, nV2, Nn, D, D);

    // ---- layer 1 ----
    init_seg_kernel<<<segBlocks, 256>>>(amax, denom, Nn);
    alpha_kernel<<<warpBlocks, 256>>>(nQ1, dst, nK1, src, dst, alpha, amax, E);
    exp_denom_kernel<<<thrBlocks, 256>>>(alpha, amax, dst, eexp, denom, E);
    attn_ln_kernel<<<warpBlocks, 256>>>(nQ1, dst, nV1, src, dst, eexp, denom, ga, ba, e0, E);
    gemm_kernel<0><<<gEdgeD, 256>>>(e0, Wff, bff, e1, E, D, D);   // query after layer 1

    // ---- layer 2 ----
    gemm_kernel<0><<<gEdgeD, 256>>>(e1, Wq + DD, bq + D, e0, E, D, D);  // q2 (edge-level)
    init_seg_kernel<<<segBlocks, 256>>>(amax, denom, Nn);
    alpha_kernel<<<warpBlocks, 256>>>(e0, nullptr, nK2, src, dst, alpha, amax, E);
    exp_denom_kernel<<<thrBlocks, 256>>>(alpha, amax, dst, eexp, denom, E);
    attn_ln_kernel<<<warpBlocks, 256>>>(e0, nullptr, nV2, src, dst, eexp, denom, ga + D, ba + D, e1, E);
    gemm_kernel<0><<<gEdgeD, 256>>>(e1, Wff + DD, bff + D, e0, E, D, D);  // query after layer 2

    // ---- head ----
    lrelu_ln_kernel<<<warpBlocks, 256>>>(e0, gf, bf, e1, E);              // queryF (kept for residual)
    gemm_kernel<1><<<gEdge3D, 256>>>(e1, W3, b3, big0, E, 3 * D, D);      // h1 = lrelu(.)
    gemm_kernel<1><<<gEdge3D, 256>>>(big0, W4, b4, big1, E, 3 * D, 3 * D);// h2 = lrelu(.)
    gemm_kernel<0><<<gEdgeD, 256>>>(big1, W5, b5, e0, E, D, 3 * D);       // h3
    final_kernel<<<warpBlocks, 256>>>(e0, e1, gfin, bfin, Wvec, bvec, out, E);

    (void)n_in; (void)out_size;
}

// round 4
// speedup vs baseline: 2.5799x; 2.5799x over previous
#include <cuda_runtime.h>
#include <cuda_bf16.h>
#include <cstdint>

#define D_MODEL 256
#define MAXE 160000
#define MAXN 10240

// ---------------- scratch (static device globals; no allocs allowed) ----------
__device__ float g_nQ1[MAXN * D_MODEL];
__device__ float g_nK1[MAXN * D_MODEL];
__device__ float g_nV1[MAXN * D_MODEL];
__device__ float g_nK2[MAXN * D_MODEL];
__device__ float g_nV2[MAXN * D_MODEL];
__device__ float g_e0[(size_t)MAXE * D_MODEL];
__device__ float g_e1[(size_t)MAXE * D_MODEL];
__device__ float g_big0[(size_t)MAXE * 3 * D_MODEL];
__device__ float g_big1[(size_t)MAXE * 3 * D_MODEL];
__device__ float g_alpha[MAXE];
__device__ float g_eexp[MAXE];
__device__ unsigned g_amax[MAXN];
__device__ float g_denom[MAXN];

// ---------------- helpers ----------------------------------------------------
__device__ __forceinline__ float warp_sum(float v) {
    #pragma unroll
    for (int o = 16; o > 0; o >>= 1) v += __shfl_xor_sync(0xFFFFFFFFu, v, o);
    return v;
}

__device__ __forceinline__ unsigned fkey(float f) {
    unsigned u = __float_as_uint(f);
    return (u & 0x80000000u) ? ~u : (u | 0x80000000u);
}
__device__ __forceinline__ float funkey(unsigned k) {
    unsigned u = (k & 0x80000000u) ? (k & 0x7FFFFFFFu) : ~k;
    return __uint_as_float(u);
}

// split two fp32 into packed bf16 hi (truncated) + bf16 lo (rounded residual).
// hi is the top 16 bits of the fp32 => v - hi is EXACT => lo captures next 8 bits.
__device__ __forceinline__ void split2(float a, float b, unsigned& hi, unsigned& lo) {
    unsigned ua = __float_as_uint(a), ub = __float_as_uint(b);
    unsigned ha = ua & 0xFFFF0000u, hb = ub & 0xFFFF0000u;
    hi = (ha >> 16) | (hb & 0xFFFF0000u);
    __nv_bfloat16 la = __float2bfloat16_rn(a - __uint_as_float(ha));
    __nv_bfloat16 lb = __float2bfloat16_rn(b - __uint_as_float(hb));
    lo = (unsigned)__bfloat16_as_ushort(la) | ((unsigned)__bfloat16_as_ushort(lb) << 16);
}

__device__ __forceinline__ void mma16816(float* c, const unsigned* a, unsigned b0, unsigned b1) {
    asm volatile(
        "mma.sync.aligned.m16n8k16.row.col.f32.bf16.bf16.f32 "
        "{%0,%1,%2,%3}, {%4,%5,%6,%7}, {%8,%9}, {%0,%1,%2,%3};\n"
        : "+f"(c[0]), "+f"(c[1]), "+f"(c[2]), "+f"(c[3])
        : "r"(a[0]), "r"(a[1]), "r"(a[2]), "r"(a[3]), "r"(b0), "r"(b1));
}

// ---------------- tensor-core GEMM: C[M,N] = act(A[M,K] @ W[N,K]^T + bias) ----
// 128x128x32 block tile, 256 threads (8 warps, 2M x 4N), warp tile 64x32.
// Split-bf16: 3 MMA passes (Ah*Wh + Al*Wh + Ah*Wl) => ~fp32 accuracy.
#define PK 40  // bf16 per smem row (32 data + 8 pad) -> 80B stride = 20 banks, conflict-free

template <int ACT>  // 0 = none, 1 = leaky relu (0.2)
__global__ __launch_bounds__(256, 2)
void gemm_mma_kernel(const float* __restrict__ A, const float* __restrict__ W,
                     const float* __restrict__ bias, float* __restrict__ C,
                     int M, int N, int K) {
    __shared__ unsigned short Ahs[128 * PK];
    __shared__ unsigned short Als[128 * PK];
    __shared__ unsigned short Bhs[128 * PK];
    __shared__ unsigned short Bls[128 * PK];

    const int tid = threadIdx.x;
    const int wid = tid >> 5, lane = tid & 31;
    const int wm = wid & 1;        // 0..1 -> 64-row half
    const int wn = wid >> 1;       // 0..3 -> 32-col quarter
    const int g = lane >> 2, t = lane & 3;
    const int bm = blockIdx.y * 128, bn = blockIdx.x * 128;

    float acc[4][4][4];
    #pragma unroll
    for (int i = 0; i < 4; i++)
        #pragma unroll
        for (int j = 0; j < 4; j++)
            #pragma unroll
            for (int r = 0; r < 4; r++) acc[i][j][r] = 0.f;

    for (int k0 = 0; k0 < K; k0 += 32) {
        __syncthreads();
        // fill smem: 128x32 fp32 tiles of A and W, split to hi/lo bf16
        #pragma unroll
        for (int p = 0; p < 4; p++) {
            int f = tid + p * 256;          // float4 index 0..1023
            int row = f >> 3;               // 0..127
            int c4 = (f & 7) * 4;           // 0,4,...,28
            int so = row * PK + c4;

            int ar = bm + row;
            float4 av = (ar < M) ? *(const float4*)(A + (size_t)ar * K + k0 + c4)
                                 : make_float4(0.f, 0.f, 0.f, 0.f);
            unsigned h0, l0, h1, l1;
            split2(av.x, av.y, h0, l0);
            split2(av.z, av.w, h1, l1);
            *(uint2*)&Ahs[so] = make_uint2(h0, h1);
            *(uint2*)&Als[so] = make_uint2(l0, l1);

            int wr = bn + row;
            float4 wv = (wr < N) ? *(const float4*)(W + (size_t)wr * K + k0 + c4)
                                 : make_float4(0.f, 0.f, 0.f, 0.f);
            split2(wv.x, wv.y, h0, l0);
            split2(wv.z, wv.w, h1, l1);
            *(uint2*)&Bhs[so] = make_uint2(h0, h1);
            *(uint2*)&Bls[so] = make_uint2(l0, l1);
        }
        __syncthreads();

        #pragma unroll
        for (int ks = 0; ks < 32; ks += 16) {
            const int c0 = ks + t * 2;
            unsigned a_hi[4][4], a_lo[4][4];
            #pragma unroll
            for (int mt = 0; mt < 4; mt++) {
                int r0 = wm * 64 + mt * 16 + g;
                a_hi[mt][0] = *(const unsigned*)&Ahs[r0 * PK + c0];
                a_hi[mt][1] = *(const unsigned*)&Ahs[(r0 + 8) * PK + c0];
                a_hi[mt][2] = *(const unsigned*)&Ahs[r0 * PK + c0 + 8];
                a_hi[mt][3] = *(const unsigned*)&Ahs[(r0 + 8) * PK + c0 + 8];
                a_lo[mt][0] = *(const unsigned*)&Als[r0 * PK + c0];
                a_lo[mt][1] = *(const unsigned*)&Als[(r0 + 8) * PK + c0];
                a_lo[mt][2] = *(const unsigned*)&Als[r0 * PK + c0 + 8];
                a_lo[mt][3] = *(const unsigned*)&Als[(r0 + 8) * PK + c0 + 8];
            }
            #pragma unroll
            for (int nt = 0; nt < 4; nt++) {
                int n0 = wn * 32 + nt * 8 + g;
                unsigned bh0 = *(const unsigned*)&Bhs[n0 * PK + c0];
                unsigned bh1 = *(const unsigned*)&Bhs[n0 * PK + c0 + 8];
                unsigned bl0 = *(const unsigned*)&Bls[n0 * PK + c0];
                unsigned bl1 = *(const unsigned*)&Bls[n0 * PK + c0 + 8];
                #pragma unroll
                for (int mt = 0; mt < 4; mt++) {
                    mma16816(acc[mt][nt], a_hi[mt], bh0, bh1);
                    mma16816(acc[mt][nt], a_lo[mt], bh0, bh1);
                    mma16816(acc[mt][nt], a_hi[mt], bl0, bl1);
                }
            }
        }
    }

    // epilogue: bias + act; c0,c1 -> (row, c),(row, c+1); c2,c3 -> row+8
    #pragma unroll
    for (int mt = 0; mt < 4; mt++) {
        #pragma unroll
        for (int nt = 0; nt < 4; nt++) {
            int r = bm + wm * 64 + mt * 16 + g;
            int c = bn + wn * 32 + nt * 8 + t * 2;
            float bi0 = bias[c], bi1 = bias[c + 1];
            #pragma unroll
            for (int half = 0; half < 2; half++) {
                int rr = r + half * 8;
                if (rr < M) {
                    float v0 = acc[mt][nt][half * 2 + 0] + bi0;
                    float v1 = acc[mt][nt][half * 2 + 1] + bi1;
                    if (ACT == 1) {
                        v0 = v0 > 0.f ? v0 : 0.2f * v0;
                        v1 = v1 > 0.f ? v1 : 0.2f * v1;
                    }
                    *(float2*)(C + (size_t)rr * N + c) = make_float2(v0, v1);
                }
            }
        }
    }
}

// ---------------- segment-softmax pieces --------------------------------------
__global__ void init_seg_kernel(unsigned* amax, float* denom, int n) {
    int i = blockIdx.x * blockDim.x + threadIdx.x;
    if (i < n) { amax[i] = 0u; denom[i] = 0.f; }
}

__global__ void alpha_kernel(const float* __restrict__ Q, const int* __restrict__ qidx,
                             const float* __restrict__ Kn,
                             const int* __restrict__ src, const int* __restrict__ dst,
                             float* __restrict__ alpha, unsigned* __restrict__ amax, int E) {
    int e = (blockIdx.x * blockDim.x + threadIdx.x) >> 5;
    int lane = threadIdx.x & 31;
    if (e >= E) return;
    const float* qr = Q + (size_t)(qidx ? qidx[e] : e) * D_MODEL;
    const float* kr = Kn + (size_t)src[e] * D_MODEL;
    float s = 0.f;
    #pragma unroll
    for (int i = 0; i < 8; i++) {
        int d = lane + 32 * i;
        s += qr[d] * kr[d];
    }
    s = warp_sum(s);
    if (lane == 0) {
        alpha[e] = s;
        atomicMax(&amax[dst[e]], fkey(s));
    }
}

__global__ void exp_denom_kernel(const float* __restrict__ alpha, const unsigned* __restrict__ amax,
                                 const int* __restrict__ dst,
                                 float* __restrict__ eexp, float* __restrict__ denom, int E) {
    int e = blockIdx.x * blockDim.x + threadIdx.x;
    if (e >= E) return;
    float m = funkey(amax[dst[e]]);
    float v = expf(alpha[e] - m);
    eexp[e] = v;
    atomicAdd(&denom[dst[e]], v);
}

__global__ void attn_ln_kernel(const float* __restrict__ Q, const int* __restrict__ qidx,
                               const float* __restrict__ Vn,
                               const int* __restrict__ src, const int* __restrict__ dst,
                               const float* __restrict__ eexp, const float* __restrict__ denom,
                               const float* __restrict__ g, const float* __restrict__ b,
                               float* __restrict__ out, int E) {
    int e = (blockIdx.x * blockDim.x + threadIdx.x) >> 5;
    int lane = threadIdx.x & 31;
    if (e >= E) return;
    const float* qr = Q + (size_t)(qidx ? qidx[e] : e) * D_MODEL;
    const float* vr = Vn + (size_t)src[e] * D_MODEL;
    float attn = eexp[e] / denom[dst[e]];
    float vals[8];
    #pragma unroll
    for (int i = 0; i < 8; i++) {
        int d = lane + 32 * i;
        vals[i] = qr[d] + attn * vr[d];
    }
    float s = 0.f;
    #pragma unroll
    for (int i = 0; i < 8; i++) s += vals[i];
    float mean = warp_sum(s) * (1.f / 256.f);
    float q2 = 0.f;
    #pragma unroll
    for (int i = 0; i < 8; i++) { float tt = vals[i] - mean; q2 += tt * tt; }
    float rstd = rsqrtf(warp_sum(q2) * (1.f / 256.f) + 1e-5f);
    float* orow = out + (size_t)e * D_MODEL;
    #pragma unroll
    for (int i = 0; i < 8; i++) {
        int d = lane + 32 * i;
        orow[d] = (vals[i] - mean) * rstd * g[d] + b[d];
    }
}

__global__ void lrelu_ln_kernel(const float* __restrict__ in,
                                const float* __restrict__ g, const float* __restrict__ b,
                                float* __restrict__ out, int E) {
    int e = (blockIdx.x * blockDim.x + threadIdx.x) >> 5;
    int lane = threadIdx.x & 31;
    if (e >= E) return;
    const float* ir = in + (size_t)e * D_MODEL;
    float vals[8];
    #pragma unroll
    for (int i = 0; i < 8; i++) {
        float v = ir[lane + 32 * i];
        vals[i] = v > 0.f ? v : 0.2f * v;
    }
    float s = 0.f;
    #pragma unroll
    for (int i = 0; i < 8; i++) s += vals[i];
    float mean = warp_sum(s) * (1.f / 256.f);
    float q2 = 0.f;
    #pragma unroll
    for (int i = 0; i < 8; i++) { float tt = vals[i] - mean; q2 += tt * tt; }
    float rstd = rsqrtf(warp_sum(q2) * (1.f / 256.f) + 1e-5f);
    float* orow = out + (size_t)e * D_MODEL;
    #pragma unroll
    for (int i = 0; i < 8; i++) {
        int d = lane + 32 * i;
        orow[d] = (vals[i] - mean) * rstd * g[d] + b[d];
    }
}

__global__ void final_kernel(const float* __restrict__ h3, const float* __restrict__ qf,
                             const float* __restrict__ g, const float* __restrict__ b,
                             const float* __restrict__ Wvec, const float* __restrict__ bvec,
                             float* __restrict__ out, int E) {
    int e = (blockIdx.x * blockDim.x + threadIdx.x) >> 5;
    int lane = threadIdx.x & 31;
    if (e >= E) return;
    const float* hr = h3 + (size_t)e * D_MODEL;
    const float* qr = qf + (size_t)e * D_MODEL;
    float vals[8];
    #pragma unroll
    for (int i = 0; i < 8; i++) {
        int d = lane + 32 * i;
        vals[i] = hr[d] + qr[d];
    }
    float s = 0.f;
    #pragma unroll
    for (int i = 0; i < 8; i++) s += vals[i];
    float mean = warp_sum(s) * (1.f / 256.f);
    float q2 = 0.f;
    #pragma unroll
    for (int i = 0; i < 8; i++) { float tt = vals[i] - mean; q2 += tt * tt; }
    float rstd = rsqrtf(warp_sum(q2) * (1.f / 256.f) + 1e-5f);
    float dotv = 0.f;
    #pragma unroll
    for (int i = 0; i < 8; i++) {
        int d = lane + 32 * i;
        float hn = (vals[i] - mean) * rstd * g[d] + b[d];
        dotv += hn * Wvec[d];
    }
    dotv = warp_sum(dotv);
    if (lane == 0) out[e] = dotv + bvec[0];
}

// ---------------- launch ------------------------------------------------------
extern "C" void kernel_launch(void* const* d_in, const int* in_sizes, int n_in,
                              void* d_out, int out_size) {
    const int*   ei   = (const int*)d_in[0];
    const float* x    = (const float*)d_in[1];
    const float* Wq   = (const float*)d_in[2];
    const float* bq   = (const float*)d_in[3];
    const float* Wk   = (const float*)d_in[4];
    const float* bk   = (const float*)d_in[5];
    const float* Wv   = (const float*)d_in[6];
    const float* bv   = (const float*)d_in[7];
    const float* Wff  = (const float*)d_in[8];
    const float* bff  = (const float*)d_in[9];
    const float* ga   = (const float*)d_in[10];
    const float* ba   = (const float*)d_in[11];
    const float* gf   = (const float*)d_in[12];
    const float* bf   = (const float*)d_in[13];
    const float* gfin = (const float*)d_in[14];
    const float* bfin = (const float*)d_in[15];
    const float* W3   = (const float*)d_in[16];
    const float* b3   = (const float*)d_in[17];
    const float* W4   = (const float*)d_in[18];
    const float* b4   = (const float*)d_in[19];
    const float* W5   = (const float*)d_in[20];
    const float* b5   = (const float*)d_in[21];
    const float* Wvec = (const float*)d_in[22];
    const float* bvec = (const float*)d_in[23];
    float* out = (float*)d_out;

    const int E  = in_sizes[0] / 2;
    const int Nn = in_sizes[1] / D_MODEL;
    const int D  = D_MODEL;
    const int DD = D * D;
    const int* src = ei;
    const int* dst = ei + E;

    float *nQ1, *nK1, *nV1, *nK2, *nV2, *e0, *e1, *big0, *big1, *alpha, *eexp, *denom;
    unsigned* amax;
    cudaGetSymbolAddress((void**)&nQ1, g_nQ1);
    cudaGetSymbolAddress((void**)&nK1, g_nK1);
    cudaGetSymbolAddress((void**)&nV1, g_nV1);
    cudaGetSymbolAddress((void**)&nK2, g_nK2);
    cudaGetSymbolAddress((void**)&nV2, g_nV2);
    cudaGetSymbolAddress((void**)&e0, g_e0);
    cudaGetSymbolAddress((void**)&e1, g_e1);
    cudaGetSymbolAddress((void**)&big0, g_big0);
    cudaGetSymbolAddress((void**)&big1, g_big1);
    cudaGetSymbolAddress((void**)&alpha, g_alpha);
    cudaGetSymbolAddress((void**)&eexp, g_eexp);
    cudaGetSymbolAddress((void**)&amax, g_amax);
    cudaGetSymbolAddress((void**)&denom, g_denom);

    dim3 gNode(D / 128, (Nn + 127) / 128);
    dim3 gEdgeD(D / 128, (E + 127) / 128);
    dim3 gEdge3D(3 * D / 128, (E + 127) / 128);
    const int warpBlocks = (E * 32 + 255) / 256;
    const int thrBlocks = (E + 255) / 256;
    const int segBlocks = (Nn + 255) / 256;

    // node-level projections (16x FLOP saving vs edge-level)
    gemm_mma_kernel<0><<<gNode, 256>>>(x, Wq,      bq,     nQ1, Nn, D, D);
    gemm_mma_kernel<0><<<gNode, 256>>>(x, Wk,      bk,     nK1, Nn, D, D);
    gemm_mma_kernel<0><<<gNode, 256>>>(x, Wv,      bv,     nV1, Nn, D, D);
    gemm_mma_kernel<0><<<gNode, 256>>>(x, Wk + DD, bk + D, nK2, Nn, D, D);
    gemm_mma_kernel<0><<<gNode, 256>>>(x, Wv + DD, bv + D, nV2, Nn, D, D);

    // ---- layer 1 ----
    init_seg_kernel<<<segBlocks, 256>>>(amax, denom, Nn);
    alpha_kernel<<<warpBlocks, 256>>>(nQ1, dst, nK1, src, dst, alpha, amax, E);
    exp_denom_kernel<<<thrBlocks, 256>>>(alpha, amax, dst, eexp, denom, E);
    attn_ln_kernel<<<warpBlocks, 256>>>(nQ1, dst, nV1, src, dst, eexp, denom, ga, ba, e0, E);
    gemm_mma_kernel<0><<<gEdgeD, 256>>>(e0, Wff, bff, e1, E, D, D);

    // ---- layer 2 ----
    gemm_mma_kernel<0><<<gEdgeD, 256>>>(e1, Wq + DD, bq + D, e0, E, D, D);  // q2 (edge-level)
    init_seg_kernel<<<segBlocks, 256>>>(amax, denom, Nn);
    alpha_kernel<<<warpBlocks, 256>>>(e0, nullptr, nK2, src, dst, alpha, amax, E);
    exp_denom_kernel<<<thrBlocks, 256>>>(alpha, amax, dst, eexp, denom, E);
    attn_ln_kernel<<<warpBlocks, 256>>>(e0, nullptr, nV2, src, dst, eexp, denom, ga + D, ba + D, e1, E);
    gemm_mma_kernel<0><<<gEdgeD, 256>>>(e1, Wff + DD, bff + D, e0, E, D, D);

    // ---- head ----
    lrelu_ln_kernel<<<warpBlocks, 256>>>(e0, gf, bf, e1, E);                   // queryF
    gemm_mma_kernel<1><<<gEdge3D, 256>>>(e1, W3, b3, big0, E, 3 * D, D);       // h1
    gemm_mma_kernel<1><<<gEdge3D, 256>>>(big0, W4, b4, big1, E, 3 * D, 3 * D); // h2
    gemm_mma_kernel<0><<<gEdgeD, 256>>>(big1, W5, b5, e0, E, D, 3 * D);        // h3
    final_kernel<<<warpBlocks, 256>>>(e0, e1, gfin, bfin, Wvec, bvec, out, E);

    (void)n_in; (void)out_size;
}